// round 2
// baseline (speedup 1.0000x reference)
#include <cuda_runtime.h>
#include <cstdint>

// ============================================================================
// Fused MaskedLSTMNetworkWithMergedEmb
//   Phase A: feature build (embedding gather + concat)  -> sA [64][242pad256]
//   GEMM1:   h1 = relu(combined @ w0 + b0)              -> sB
//   GEMM2:   x  = relu(h1 @ w1 + b1)                    -> sA
//   Gates:   [x | h_in] @ wT (pre-transposed) + biases, 4 chunks (i,g,f,o)
//   LSTM elementwise + logits head + mask, all in registers.
// fp32 math throughout via packed fma.rn.f32x2 (FFMA2, 2 MAC/inst).
// R1 fix: dynamic SMEM size was 192 floats short of the sIds region -> OOB.
// ============================================================================

#define TM   64          // rows per CTA
#define KT   16          // k-tile
#define AST  260         // smem activation row stride (floats)
#define NTHR 256

typedef unsigned long long ull;

// scratch: wT[k][g], k<256 -> w_ih[g][k], k>=256 -> w_hh[g][k-256]
__device__ float g_wT[512 * 1024];

__constant__ int c_cont[20] = {162,163,164,165, 17, 19,20,21, 22,
                               166,167,168,169, 93, 95,96,97, 98, 152,153};

__device__ __forceinline__ ull pk2(float lo, float hi) {
    ull r; asm("mov.b64 %0,{%1,%2};" : "=l"(r) : "f"(lo), "f"(hi)); return r;
}
__device__ __forceinline__ void upk2(ull v, float& lo, float& hi) {
    asm("mov.b64 {%0,%1},%2;" : "=f"(lo), "=f"(hi) : "l"(v));
}
__device__ __forceinline__ void ffma2(ull& c, ull a, ull b) {
    asm("fma.rn.f32x2 %0, %1, %2, %0;" : "+l"(c) : "l"(a), "l"(b));
}
__device__ __forceinline__ void unpack8(const ull a[4], float v[8]) {
    upk2(a[0], v[0], v[1]); upk2(a[1], v[2], v[3]);
    upk2(a[2], v[4], v[5]); upk2(a[3], v[6], v[7]);
}
__device__ __forceinline__ float sigm(float x) { return 1.f / (1.f + __expf(-x)); }
__device__ __forceinline__ float tanh_(float x) {
    float t = __expf(-2.f * fabsf(x));
    float r = (1.f - t) / (1.f + t);
    return copysignf(r, x);
}

// ----------------------------------------------------------------------------
// Transpose/concat w_ih,w_hh -> g_wT[k][g] (k-major for coalesced tile loads)
// ----------------------------------------------------------------------------
__global__ void mlstm_prep_kernel(const float* __restrict__ w_ih,
                                  const float* __restrict__ w_hh) {
    int idx = blockIdx.x * blockDim.x + threadIdx.x;   // 512*1024 total
    int k = idx >> 10, g = idx & 1023;
    g_wT[idx] = (k < 256) ? w_ih[g * 256 + k] : w_hh[g * 256 + (k - 256)];
}

// ----------------------------------------------------------------------------
// Block GEMM: acc[8][4](packed pairs) = A[64 x ktot] * W[ktot x 256 slice]
//   A rows in smem (stride AST), warp-uniform broadcast reads.
//   W streamed in [KT][256] smem tiles from global (k-major, coalesced).
//   Thread (ty,tx): rows ty*8..+7, cols {tx*4..+3, 128+tx*4..+3}.
// ----------------------------------------------------------------------------
__device__ __forceinline__ void gemm_block(
    const float* __restrict__ Wg, int ldw, int coff, int kvalid, int ktot,
    const float* A0, const float* A1,
    float* sW, int tid, int tx, int ty, ull acc[8][4])
{
#pragma unroll
    for (int i = 0; i < 8; i++)
#pragma unroll
        for (int j = 0; j < 4; j++) acc[i][j] = pk2(0.f, 0.f);

    for (int k0 = 0; k0 < ktot; k0 += KT) {
        // stage weight tile [KT][256]
#pragma unroll
        for (int t = 0; t < (KT * 256 / 4) / NTHR; t++) {
            int s = tid + t * NTHR;           // float4 slot
            int ks = s >> 6, c4 = s & 63;
            int k = k0 + ks;
            float4 v = make_float4(0.f, 0.f, 0.f, 0.f);
            if (k < kvalid)
                v = *(const float4*)(Wg + (size_t)k * ldw + coff + c4 * 4);
            *(float4*)(sW + ks * 256 + c4 * 4) = v;
        }
        __syncthreads();

        const float* As = (A1 != nullptr && k0 >= 256) ? (A1 + (k0 - 256)) : (A0 + k0);
        const float* Arow = As + ty * 8 * AST;

#pragma unroll
        for (int ks = 0; ks < KT; ks += 4) {
            float4 av[8];
#pragma unroll
            for (int i = 0; i < 8; i++)
                av[i] = *(const float4*)(Arow + i * AST + ks);
#pragma unroll
            for (int s = 0; s < 4; s++) {
                float4 b0 = *(const float4*)(sW + (ks + s) * 256 + tx * 4);
                float4 b1 = *(const float4*)(sW + (ks + s) * 256 + 128 + tx * 4);
                ull bp0 = pk2(b0.x, b0.y), bp1 = pk2(b0.z, b0.w);
                ull bp2 = pk2(b1.x, b1.y), bp3 = pk2(b1.z, b1.w);
#pragma unroll
                for (int i = 0; i < 8; i++) {
                    float a = (s == 0) ? av[i].x : (s == 1) ? av[i].y
                             : (s == 2) ? av[i].z : av[i].w;
                    ull ap = pk2(a, a);
                    ffma2(acc[i][0], ap, bp0);
                    ffma2(acc[i][1], ap, bp1);
                    ffma2(acc[i][2], ap, bp2);
                    ffma2(acc[i][3], ap, bp3);
                }
            }
        }
        __syncthreads();
    }
}

// ----------------------------------------------------------------------------
__global__ __launch_bounds__(NTHR, 1) void mlstm_fused_kernel(
    const float* __restrict__ inputs,  const float* __restrict__ h_in,
    const float* __restrict__ c_in,    const float* __restrict__ prof_emb,
    const float* __restrict__ skill_emb, const float* __restrict__ eff_emb,
    const float* __restrict__ w0, const float* __restrict__ b0,
    const float* __restrict__ w1, const float* __restrict__ b1,
    const float* __restrict__ b_ih, const float* __restrict__ b_hh,
    const float* __restrict__ w_logits, const float* __restrict__ b_logits,
    float* __restrict__ out, int B)
{
    extern __shared__ float sm[];
    float* sA  = sm;                 // [64][AST]
    float* sH  = sA + TM * AST;      // [64][AST]  h_in
    float* sB  = sH + TM * AST;      // [64][AST]  (aliased as sIn during build)
    float* sW  = sB + TM * AST;      // [KT][256]
    float* sWl = sW + KT * 256;      // [256][4]
    int*  sIds = (int*)(sWl + 1024); // [64][4] = 256 ints
    float* sIn = sB;                 // alias, stride 172

    const int tid = threadIdx.x;
    const int tx = tid & 31, ty = tid >> 5;
    const int r0 = blockIdx.x * TM;

    // ---- stage inputs rows (contiguous), h_in, w_logits -------------------
    for (int i = tid; i < TM * 170; i += NTHR) {
        int r = i / 170, c = i - r * 170;
        sIn[r * 172 + c] = inputs[(size_t)r0 * 170 + i];
    }
    for (int i = tid; i < TM * 256; i += NTHR) {
        int r = i >> 8, c = i & 255;
        sH[r * AST + c] = h_in[(size_t)(r0 + r) * 256 + c];
    }
    for (int i = tid; i < 1024; i += NTHR) sWl[i] = w_logits[i];
    __syncthreads();

    // ---- per-row argmax ids ----------------------------------------------
    if (tid < TM) {
        const float* row = sIn + tid * 172;
        int pp = 0; float bv = row[4];
#pragma unroll
        for (int k = 1; k < 13; k++) { float v = row[4 + k];  if (v > bv) { bv = v; pp = k; } }
        int pe = 0; bv = row[80];
#pragma unroll
        for (int k = 1; k < 13; k++) { float v = row[80 + k]; if (v > bv) { bv = v; pe = k; } }
        int sp = 0; bv = row[158];
#pragma unroll
        for (int k = 1; k < 4; k++)  { float v = row[158 + k]; if (v > bv) { bv = v; sp = k; } }
        int se = 0; bv = row[154];
#pragma unroll
        for (int k = 1; k < 4; k++)  { float v = row[154 + k]; if (v > bv) { bv = v; se = k; } }
        sIds[tid * 4 + 0] = pp;
        sIds[tid * 4 + 1] = pe;
        sIds[tid * 4 + 2] = pp * 4 + sp;
        sIds[tid * 4 + 3] = pe * 4 + se;
    }
    __syncthreads();

    // ---- build combined[242] (padded to 256 with zeros) ------------------
    for (int i = tid; i < TM * 256; i += NTHR) {
        int r = i >> 8, k = i & 255;
        const float* row = sIn + r * 172;
        float v = 0.f;
        if (k < 16) {
            int id = sIds[r * 4 + (k >> 3)];
            v = prof_emb[id * 8 + (k & 7)];
        } else if (k < 40) {
            int id, off;
            if (k < 28) { id = sIds[r * 4 + 2]; off = k - 16; }
            else        { id = sIds[r * 4 + 3]; off = k - 28; }
            v = skill_emb[id * 12 + off];
        } else if (k < 222) {
            int k2, st;
            if (k < 131) { k2 = k - 40;  st = 37;  }
            else         { k2 = k - 131; st = 113; }
            int j = k2 / 7, m = k2 - j * 7;
            v = (m < 4) ? eff_emb[j * 4 + m] : row[st + 3 * j + (m - 4)];
        } else if (k < 242) {
            v = row[c_cont[k - 222]];
        }
        sA[r * AST + k] = v;
    }
    __syncthreads();

    ull acc[8][4];
    const int c0 = tx * 4, c1 = 128 + tx * 4;

    // ---- GEMM1: h1 = relu(combined @ w0 + b0) -> sB ----------------------
    gemm_block(w0, 256, 0, 242, 256, sA, nullptr, sW, tid, tx, ty, acc);
    {
        float bb[8];
#pragma unroll
        for (int e = 0; e < 4; e++) { bb[e] = b0[c0 + e]; bb[4 + e] = b0[c1 + e]; }
#pragma unroll
        for (int i = 0; i < 8; i++) {
            float v[8]; unpack8(acc[i], v);
            float* dst = sB + (ty * 8 + i) * AST;
            *(float4*)(dst + c0) = make_float4(fmaxf(v[0] + bb[0], 0.f), fmaxf(v[1] + bb[1], 0.f),
                                               fmaxf(v[2] + bb[2], 0.f), fmaxf(v[3] + bb[3], 0.f));
            *(float4*)(dst + c1) = make_float4(fmaxf(v[4] + bb[4], 0.f), fmaxf(v[5] + bb[5], 0.f),
                                               fmaxf(v[6] + bb[6], 0.f), fmaxf(v[7] + bb[7], 0.f));
        }
    }
    __syncthreads();

    // ---- GEMM2: x = relu(h1 @ w1 + b1) -> sA -----------------------------
    gemm_block(w1, 256, 0, 256, 256, sB, nullptr, sW, tid, tx, ty, acc);
    {
        float bb[8];
#pragma unroll
        for (int e = 0; e < 4; e++) { bb[e] = b1[c0 + e]; bb[4 + e] = b1[c1 + e]; }
#pragma unroll
        for (int i = 0; i < 8; i++) {
            float v[8]; unpack8(acc[i], v);
            float* dst = sA + (ty * 8 + i) * AST;
            *(float4*)(dst + c0) = make_float4(fmaxf(v[0] + bb[0], 0.f), fmaxf(v[1] + bb[1], 0.f),
                                               fmaxf(v[2] + bb[2], 0.f), fmaxf(v[3] + bb[3], 0.f));
            *(float4*)(dst + c1) = make_float4(fmaxf(v[4] + bb[4], 0.f), fmaxf(v[5] + bb[5], 0.f),
                                               fmaxf(v[6] + bb[6], 0.f), fmaxf(v[7] + bb[7], 0.f));
        }
    }
    __syncthreads();

    // ---- Gate chunks over K=512 ([x | h_in] @ g_wT slice) ----------------
    float ti[8][8];   // running elementwise state

    // i gate (chunk 0)
    gemm_block(g_wT, 1024, 0, 512, 512, sA, sH, sW, tid, tx, ty, acc);
    {
        float bb[8];
#pragma unroll
        for (int e = 0; e < 4; e++) {
            bb[e]     = b_ih[c0 + e]       + b_hh[c0 + e];
            bb[4 + e] = b_ih[c1 + e]       + b_hh[c1 + e];
        }
#pragma unroll
        for (int i = 0; i < 8; i++) {
            float v[8]; unpack8(acc[i], v);
#pragma unroll
            for (int e = 0; e < 8; e++) ti[i][e] = sigm(v[e] + bb[e]);
        }
    }

    // g gate (chunk 2) : ti = sig(i)*tanh(g)
    gemm_block(g_wT, 1024, 2 * 256, 512, 512, sA, sH, sW, tid, tx, ty, acc);
    {
        float bb[8];
#pragma unroll
        for (int e = 0; e < 4; e++) {
            bb[e]     = b_ih[512 + c0 + e] + b_hh[512 + c0 + e];
            bb[4 + e] = b_ih[512 + c1 + e] + b_hh[512 + c1 + e];
        }
#pragma unroll
        for (int i = 0; i < 8; i++) {
            float v[8]; unpack8(acc[i], v);
#pragma unroll
            for (int e = 0; e < 8; e++) ti[i][e] *= tanh_(v[e] + bb[e]);
        }
    }

    // f gate (chunk 1) : ti = sig(f)*c_in + ti   (-> c_out)
    gemm_block(g_wT, 1024, 1 * 256, 512, 512, sA, sH, sW, tid, tx, ty, acc);
    {
        float bb[8];
#pragma unroll
        for (int e = 0; e < 4; e++) {
            bb[e]     = b_ih[256 + c0 + e] + b_hh[256 + c0 + e];
            bb[4 + e] = b_ih[256 + c1 + e] + b_hh[256 + c1 + e];
        }
#pragma unroll
        for (int i = 0; i < 8; i++) {
            float v[8]; unpack8(acc[i], v);
            const float* cr = c_in + (size_t)(r0 + ty * 8 + i) * 256;
            float4 ci0 = *(const float4*)(cr + c0);
            float4 ci1 = *(const float4*)(cr + c1);
            ti[i][0] = sigm(v[0] + bb[0]) * ci0.x + ti[i][0];
            ti[i][1] = sigm(v[1] + bb[1]) * ci0.y + ti[i][1];
            ti[i][2] = sigm(v[2] + bb[2]) * ci0.z + ti[i][2];
            ti[i][3] = sigm(v[3] + bb[3]) * ci0.w + ti[i][3];
            ti[i][4] = sigm(v[4] + bb[4]) * ci1.x + ti[i][4];
            ti[i][5] = sigm(v[5] + bb[5]) * ci1.y + ti[i][5];
            ti[i][6] = sigm(v[6] + bb[6]) * ci1.z + ti[i][6];
            ti[i][7] = sigm(v[7] + bb[7]) * ci1.w + ti[i][7];
        }
    }

    // o gate (chunk 3) : h = sig(o)*tanh(c_out); store c_out,h; ti <- h
    gemm_block(g_wT, 1024, 3 * 256, 512, 512, sA, sH, sW, tid, tx, ty, acc);
    {
        float* out_h = out + (size_t)B * 4;
        float* out_c = out_h + (size_t)B * 256;
        float bb[8];
#pragma unroll
        for (int e = 0; e < 4; e++) {
            bb[e]     = b_ih[768 + c0 + e] + b_hh[768 + c0 + e];
            bb[4 + e] = b_ih[768 + c1 + e] + b_hh[768 + c1 + e];
        }
#pragma unroll
        for (int i = 0; i < 8; i++) {
            int gr = r0 + ty * 8 + i;
            float v[8]; unpack8(acc[i], v);
            float h[8];
#pragma unroll
            for (int e = 0; e < 8; e++)
                h[e] = sigm(v[e] + bb[e]) * tanh_(ti[i][e]);
            *(float4*)(out_c + (size_t)gr * 256 + c0) = make_float4(ti[i][0], ti[i][1], ti[i][2], ti[i][3]);
            *(float4*)(out_c + (size_t)gr * 256 + c1) = make_float4(ti[i][4], ti[i][5], ti[i][6], ti[i][7]);
            *(float4*)(out_h + (size_t)gr * 256 + c0) = make_float4(h[0], h[1], h[2], h[3]);
            *(float4*)(out_h + (size_t)gr * 256 + c1) = make_float4(h[4], h[5], h[6], h[7]);
#pragma unroll
            for (int e = 0; e < 8; e++) ti[i][e] = h[e];
        }
    }

    // ---- logits head + mask ----------------------------------------------
    float pl[8][4];
#pragma unroll
    for (int i = 0; i < 8; i++)
#pragma unroll
        for (int l = 0; l < 4; l++) pl[i][l] = 0.f;
#pragma unroll
    for (int i = 0; i < 8; i++) {
#pragma unroll
        for (int e = 0; e < 8; e++) {
            int c = (e < 4) ? (c0 + e) : (c1 + e - 4);
            float hv = ti[i][e];
#pragma unroll
            for (int l = 0; l < 4; l++) pl[i][l] += hv * sWl[c * 4 + l];
        }
    }
#pragma unroll
    for (int off = 16; off > 0; off >>= 1) {
#pragma unroll
        for (int i = 0; i < 8; i++)
#pragma unroll
            for (int l = 0; l < 4; l++)
                pl[i][l] += __shfl_down_sync(0xffffffffu, pl[i][l], off);
    }
    if (tx == 0) {
#pragma unroll
        for (int i = 0; i < 8; i++) {
            int gr = r0 + ty * 8 + i;
            const float* mrow = inputs + (size_t)gr * 170;
#pragma unroll
            for (int l = 0; l < 4; l++) {
                float lg = pl[i][l] + b_logits[l];
                out[(size_t)gr * 4 + l] = lg + (1.f - mrow[l]) * -10000000000.0f;
            }
        }
    }
}

// ----------------------------------------------------------------------------
extern "C" void kernel_launch(void* const* d_in, const int* in_sizes, int n_in,
                              void* d_out, int out_size) {
    const float* inputs    = (const float*)d_in[0];
    const float* h_in      = (const float*)d_in[1];
    const float* c_in      = (const float*)d_in[2];
    const float* prof_emb  = (const float*)d_in[3];
    const float* skill_emb = (const float*)d_in[4];
    const float* eff_emb   = (const float*)d_in[5];
    const float* w0        = (const float*)d_in[6];
    const float* b0        = (const float*)d_in[7];
    const float* w1        = (const float*)d_in[8];
    const float* b1        = (const float*)d_in[9];
    const float* w_ih      = (const float*)d_in[10];
    const float* w_hh      = (const float*)d_in[11];
    const float* b_ih      = (const float*)d_in[12];
    const float* b_hh      = (const float*)d_in[13];
    const float* w_logits  = (const float*)d_in[14];
    const float* b_logits  = (const float*)d_in[15];
    float* out = (float*)d_out;

    int B = in_sizes[0] / 170;

    // layout: 3*TM*AST (sA,sH,sB) + KT*256 (sW) + 1024 (sWl) + 256 (sIds) + pad
    const int smem_bytes = (3 * TM * AST + KT * 256 + 1024 + 256 + 16) * 4; // 221248 B
    cudaFuncSetAttribute(mlstm_fused_kernel,
                         cudaFuncAttributeMaxDynamicSharedMemorySize, smem_bytes);

    mlstm_prep_kernel<<<(512 * 1024) / NTHR, NTHR>>>(w_ih, w_hh);
    mlstm_fused_kernel<<<B / TM, NTHR, smem_bytes>>>(
        inputs, h_in, c_in, prof_emb, skill_emb, eff_emb,
        w0, b0, w1, b1, b_ih, b_hh, w_logits, b_logits, out, B);
}

// round 3
// speedup vs baseline: 1.0886x; 1.0886x over previous
#include <cuda_runtime.h>
#include <cstdint>

// ============================================================================
// Fused MaskedLSTMNetworkWithMergedEmb — R3
//   512 threads/CTA (16 warps), 8x4 micro-tile, register-prefetched weight
//   tiles (LDG early / STS late), single in-place activation buffer.
// fp32 math via packed fma.rn.f32x2.
// ============================================================================

#define TM   64          // rows per CTA
#define KT   16          // k-tile
#define AST  260         // smem activation row stride (floats)
#define NTHR 512

typedef unsigned long long ull;

// scratch: wT[k][g], k<256 -> w_ih[g][k], k>=256 -> w_hh[g][k-256]
__device__ float g_wT[512 * 1024];

__constant__ int c_cont[20] = {162,163,164,165, 17, 19,20,21, 22,
                               166,167,168,169, 93, 95,96,97, 98, 152,153};

__device__ __forceinline__ ull pk2(float lo, float hi) {
    ull r; asm("mov.b64 %0,{%1,%2};" : "=l"(r) : "f"(lo), "f"(hi)); return r;
}
__device__ __forceinline__ void upk2(ull v, float& lo, float& hi) {
    asm("mov.b64 {%0,%1},%2;" : "=f"(lo), "=f"(hi) : "l"(v));
}
__device__ __forceinline__ void ffma2(ull& c, ull a, ull b) {
    asm("fma.rn.f32x2 %0, %1, %2, %0;" : "+l"(c) : "l"(a), "l"(b));
}
__device__ __forceinline__ float sigm(float x) { return 1.f / (1.f + __expf(-x)); }
__device__ __forceinline__ float tanh_(float x) {
    float t = __expf(-2.f * fabsf(x));
    float r = (1.f - t) / (1.f + t);
    return copysignf(r, x);
}

// ----------------------------------------------------------------------------
__global__ void mlstm_prep_kernel(const float* __restrict__ w_ih,
                                  const float* __restrict__ w_hh) {
    int idx = blockIdx.x * blockDim.x + threadIdx.x;   // 512*1024 total
    int k = idx >> 10, g = idx & 1023;
    g_wT[idx] = (k < 256) ? w_ih[g * 256 + k] : w_hh[g * 256 + (k - 256)];
}

// ----------------------------------------------------------------------------
// acc[8][2] (packed col pairs) += A[64 x ktot] * W[ktot x 256 slice]
// Thread: rows rg*8..+7, cols c0..c0+3.  Weight tile [KT][256] prefetched
// into regs (2 float4/thread) one tile ahead.
// ----------------------------------------------------------------------------
__device__ __forceinline__ void gemm_block(
    const float* __restrict__ Wg, int ldw, int coff, int kvalid, int ktot,
    const float* A0, const float* A1,
    float* sW, int tid, int c0, int rg, ull acc[8][2])
{
#pragma unroll
    for (int i = 0; i < 8; i++) { acc[i][0] = 0ull; acc[i][1] = 0ull; }

    const int ks0 = tid >> 6;          // 0..7  (slot1 = ks0+8)
    const int c40 = (tid & 63) * 4;

    float4 pf0, pf1;
    {
        int k = ks0;
        pf0 = (k < kvalid) ? *(const float4*)(Wg + (size_t)k * ldw + coff + c40)
                           : make_float4(0.f, 0.f, 0.f, 0.f);
        k = ks0 + 8;
        pf1 = (k < kvalid) ? *(const float4*)(Wg + (size_t)k * ldw + coff + c40)
                           : make_float4(0.f, 0.f, 0.f, 0.f);
    }

    for (int k0 = 0; k0 < ktot; k0 += KT) {
        __syncthreads();                       // prev tile fully consumed
        *(float4*)(sW + ks0 * 256 + c40)       = pf0;
        *(float4*)(sW + (ks0 + 8) * 256 + c40) = pf1;
        int kn = k0 + KT;
        if (kn < ktot) {
            int k = kn + ks0;
            pf0 = (k < kvalid) ? *(const float4*)(Wg + (size_t)k * ldw + coff + c40)
                               : make_float4(0.f, 0.f, 0.f, 0.f);
            k = kn + ks0 + 8;
            pf1 = (k < kvalid) ? *(const float4*)(Wg + (size_t)k * ldw + coff + c40)
                               : make_float4(0.f, 0.f, 0.f, 0.f);
        }
        __syncthreads();                       // tile visible

        const float* Ab = (A1 != nullptr && k0 >= 256) ? (A1 + (k0 - 256)) : (A0 + k0);
        const float* Ar = Ab + rg * 8 * AST;

#pragma unroll
        for (int g4 = 0; g4 < 4; g4++) {
            ull bp[8];
#pragma unroll
            for (int s = 0; s < 4; s++) {
                float4 b = *(const float4*)(sW + (g4 * 4 + s) * 256 + c0);
                bp[2 * s]     = pk2(b.x, b.y);
                bp[2 * s + 1] = pk2(b.z, b.w);
            }
#pragma unroll
            for (int i = 0; i < 8; i++) {
                float4 a = *(const float4*)(Ar + i * AST + g4 * 4);
                ull ax = pk2(a.x, a.x), ay = pk2(a.y, a.y);
                ull az = pk2(a.z, a.z), aw = pk2(a.w, a.w);
                ffma2(acc[i][0], ax, bp[0]); ffma2(acc[i][1], ax, bp[1]);
                ffma2(acc[i][0], ay, bp[2]); ffma2(acc[i][1], ay, bp[3]);
                ffma2(acc[i][0], az, bp[4]); ffma2(acc[i][1], az, bp[5]);
                ffma2(acc[i][0], aw, bp[6]); ffma2(acc[i][1], aw, bp[7]);
            }
        }
    }
}

// ----------------------------------------------------------------------------
__global__ __launch_bounds__(NTHR, 1) void mlstm_fused_kernel(
    const float* __restrict__ inputs,  const float* __restrict__ h_in,
    const float* __restrict__ c_in,    const float* __restrict__ prof_emb,
    const float* __restrict__ skill_emb, const float* __restrict__ eff_emb,
    const float* __restrict__ w0, const float* __restrict__ b0,
    const float* __restrict__ w1, const float* __restrict__ b1,
    const float* __restrict__ b_ih, const float* __restrict__ b_hh,
    const float* __restrict__ w_logits, const float* __restrict__ b_logits,
    float* __restrict__ out, int B)
{
    extern __shared__ float sm[];
    float* sX  = sm;                   // [64][AST] combined -> h1 -> x -> h
    float* sH  = sX + TM * AST;        // [64][AST] h_in
    float* sW  = sH + TM * AST;        // [KT][256]
    float* sWl = sW + KT * 256;        // [256][4]
    int*  sIds = (int*)(sWl + 1024);   // [64][4]
    float* sIn = (float*)(sIds + 256); // [64][172]

    const int tid = threadIdx.x;
    const int c0 = (tid & 63) * 4;     // 4 output cols
    const int rg = tid >> 6;           // row group (8 rows)
    const int r0 = blockIdx.x * TM;

    // ---- stage inputs, h_in, w_logits ------------------------------------
    for (int i = tid; i < TM * 170; i += NTHR) {
        int r = i / 170, c = i - r * 170;
        sIn[r * 172 + c] = inputs[(size_t)r0 * 170 + i];
    }
    for (int i = tid; i < TM * 256; i += NTHR) {
        int r = i >> 8, c = i & 255;
        sH[r * AST + c] = h_in[(size_t)(r0 + r) * 256 + c];
    }
    for (int i = tid; i < 1024; i += NTHR) sWl[i] = w_logits[i];
    __syncthreads();

    // ---- per-row argmax ids ----------------------------------------------
    if (tid < TM) {
        const float* row = sIn + tid * 172;
        int pp = 0; float bv = row[4];
#pragma unroll
        for (int k = 1; k < 13; k++) { float v = row[4 + k];  if (v > bv) { bv = v; pp = k; } }
        int pe = 0; bv = row[80];
#pragma unroll
        for (int k = 1; k < 13; k++) { float v = row[80 + k]; if (v > bv) { bv = v; pe = k; } }
        int sp = 0; bv = row[158];
#pragma unroll
        for (int k = 1; k < 4; k++)  { float v = row[158 + k]; if (v > bv) { bv = v; sp = k; } }
        int se = 0; bv = row[154];
#pragma unroll
        for (int k = 1; k < 4; k++)  { float v = row[154 + k]; if (v > bv) { bv = v; se = k; } }
        sIds[tid * 4 + 0] = pp;
        sIds[tid * 4 + 1] = pe;
        sIds[tid * 4 + 2] = pp * 4 + sp;
        sIds[tid * 4 + 3] = pe * 4 + se;
    }
    __syncthreads();

    // ---- build combined[242] (pad to 256) --------------------------------
    for (int i = tid; i < TM * 256; i += NTHR) {
        int r = i >> 8, k = i & 255;
        const float* row = sIn + r * 172;
        float v = 0.f;
        if (k < 16) {
            int id = sIds[r * 4 + (k >> 3)];
            v = prof_emb[id * 8 + (k & 7)];
        } else if (k < 40) {
            int id, off;
            if (k < 28) { id = sIds[r * 4 + 2]; off = k - 16; }
            else        { id = sIds[r * 4 + 3]; off = k - 28; }
            v = skill_emb[id * 12 + off];
        } else if (k < 222) {
            int k2, st;
            if (k < 131) { k2 = k - 40;  st = 37;  }
            else         { k2 = k - 131; st = 113; }
            int j = k2 / 7, m = k2 - j * 7;
            v = (m < 4) ? eff_emb[j * 4 + m] : row[st + 3 * j + (m - 4)];
        } else if (k < 242) {
            v = row[c_cont[k - 222]];
        }
        sX[r * AST + k] = v;
    }
    __syncthreads();

    ull acc[8][2];

    // ---- GEMM1: h1 = relu(combined @ w0 + b0) -> sX (in place) -----------
    gemm_block(w0, 256, 0, 242, 256, sX, nullptr, sW, tid, c0, rg, acc);
    __syncthreads();
    {
        float bb0 = b0[c0], bb1 = b0[c0 + 1], bb2 = b0[c0 + 2], bb3 = b0[c0 + 3];
#pragma unroll
        for (int i = 0; i < 8; i++) {
            float v0, v1, v2, v3;
            upk2(acc[i][0], v0, v1); upk2(acc[i][1], v2, v3);
            *(float4*)(sX + (rg * 8 + i) * AST + c0) =
                make_float4(fmaxf(v0 + bb0, 0.f), fmaxf(v1 + bb1, 0.f),
                            fmaxf(v2 + bb2, 0.f), fmaxf(v3 + bb3, 0.f));
        }
    }
    __syncthreads();

    // ---- GEMM2: x = relu(h1 @ w1 + b1) -> sX (in place) ------------------
    gemm_block(w1, 256, 0, 256, 256, sX, nullptr, sW, tid, c0, rg, acc);
    __syncthreads();
    {
        float bb0 = b1[c0], bb1 = b1[c0 + 1], bb2 = b1[c0 + 2], bb3 = b1[c0 + 3];
#pragma unroll
        for (int i = 0; i < 8; i++) {
            float v0, v1, v2, v3;
            upk2(acc[i][0], v0, v1); upk2(acc[i][1], v2, v3);
            *(float4*)(sX + (rg * 8 + i) * AST + c0) =
                make_float4(fmaxf(v0 + bb0, 0.f), fmaxf(v1 + bb1, 0.f),
                            fmaxf(v2 + bb2, 0.f), fmaxf(v3 + bb3, 0.f));
        }
    }
    __syncthreads();

    // ---- Gate passes over K=512 ([x | h_in] @ g_wT cols) -----------------
    float ti[8][4];   // running elementwise state

    // i gate
    gemm_block(g_wT, 1024, 0, 512, 512, sX, sH, sW, tid, c0, rg, acc);
    {
        float bb0 = b_ih[c0]     + b_hh[c0],     bb1 = b_ih[c0 + 1] + b_hh[c0 + 1];
        float bb2 = b_ih[c0 + 2] + b_hh[c0 + 2], bb3 = b_ih[c0 + 3] + b_hh[c0 + 3];
#pragma unroll
        for (int i = 0; i < 8; i++) {
            float v0, v1, v2, v3;
            upk2(acc[i][0], v0, v1); upk2(acc[i][1], v2, v3);
            ti[i][0] = sigm(v0 + bb0); ti[i][1] = sigm(v1 + bb1);
            ti[i][2] = sigm(v2 + bb2); ti[i][3] = sigm(v3 + bb3);
        }
    }

    // g gate : ti = sig(i)*tanh(g)
    gemm_block(g_wT, 1024, 512, 512, 512, sX, sH, sW, tid, c0, rg, acc);
    {
        int go = 512;
        float bb0 = b_ih[go + c0]     + b_hh[go + c0];
        float bb1 = b_ih[go + c0 + 1] + b_hh[go + c0 + 1];
        float bb2 = b_ih[go + c0 + 2] + b_hh[go + c0 + 2];
        float bb3 = b_ih[go + c0 + 3] + b_hh[go + c0 + 3];
#pragma unroll
        for (int i = 0; i < 8; i++) {
            float v0, v1, v2, v3;
            upk2(acc[i][0], v0, v1); upk2(acc[i][1], v2, v3);
            ti[i][0] *= tanh_(v0 + bb0); ti[i][1] *= tanh_(v1 + bb1);
            ti[i][2] *= tanh_(v2 + bb2); ti[i][3] *= tanh_(v3 + bb3);
        }
    }

    // f gate : ti = sig(f)*c_in + ti  (-> c_out)
    gemm_block(g_wT, 1024, 256, 512, 512, sX, sH, sW, tid, c0, rg, acc);
    {
        int go = 256;
        float bb0 = b_ih[go + c0]     + b_hh[go + c0];
        float bb1 = b_ih[go + c0 + 1] + b_hh[go + c0 + 1];
        float bb2 = b_ih[go + c0 + 2] + b_hh[go + c0 + 2];
        float bb3 = b_ih[go + c0 + 3] + b_hh[go + c0 + 3];
#pragma unroll
        for (int i = 0; i < 8; i++) {
            float v0, v1, v2, v3;
            upk2(acc[i][0], v0, v1); upk2(acc[i][1], v2, v3);
            float4 ci = *(const float4*)(c_in + (size_t)(r0 + rg * 8 + i) * 256 + c0);
            ti[i][0] = sigm(v0 + bb0) * ci.x + ti[i][0];
            ti[i][1] = sigm(v1 + bb1) * ci.y + ti[i][1];
            ti[i][2] = sigm(v2 + bb2) * ci.z + ti[i][2];
            ti[i][3] = sigm(v3 + bb3) * ci.w + ti[i][3];
        }
    }

    // o gate : h = sig(o)*tanh(c_out); store c_out, h_out; stash h in sX
    gemm_block(g_wT, 1024, 768, 512, 512, sX, sH, sW, tid, c0, rg, acc);
    float hv[8][4];
    {
        int go = 768;
        float* out_h = out + (size_t)B * 4;
        float* out_c = out_h + (size_t)B * 256;
        float bb0 = b_ih[go + c0]     + b_hh[go + c0];
        float bb1 = b_ih[go + c0 + 1] + b_hh[go + c0 + 1];
        float bb2 = b_ih[go + c0 + 2] + b_hh[go + c0 + 2];
        float bb3 = b_ih[go + c0 + 3] + b_hh[go + c0 + 3];
#pragma unroll
        for (int i = 0; i < 8; i++) {
            int gr = r0 + rg * 8 + i;
            float v0, v1, v2, v3;
            upk2(acc[i][0], v0, v1); upk2(acc[i][1], v2, v3);
            hv[i][0] = sigm(v0 + bb0) * tanh_(ti[i][0]);
            hv[i][1] = sigm(v1 + bb1) * tanh_(ti[i][1]);
            hv[i][2] = sigm(v2 + bb2) * tanh_(ti[i][2]);
            hv[i][3] = sigm(v3 + bb3) * tanh_(ti[i][3]);
            *(float4*)(out_c + (size_t)gr * 256 + c0) =
                make_float4(ti[i][0], ti[i][1], ti[i][2], ti[i][3]);
            *(float4*)(out_h + (size_t)gr * 256 + c0) =
                make_float4(hv[i][0], hv[i][1], hv[i][2], hv[i][3]);
        }
    }

    // ---- logits head + mask (h staged into sX) ---------------------------
    __syncthreads();                      // all o-gate reads of sX complete
#pragma unroll
    for (int i = 0; i < 8; i++)
        *(float4*)(sX + (rg * 8 + i) * AST + c0) =
            make_float4(hv[i][0], hv[i][1], hv[i][2], hv[i][3]);
    __syncthreads();

    if (tid < TM * 4) {
        int row = tid >> 2, l = tid & 3;
        const float* xr = sX + row * AST;
        float s = 0.f;
#pragma unroll 8
        for (int c = 0; c < 256; c++) s += xr[c] * sWl[c * 4 + l];
        float m = inputs[(size_t)(r0 + row) * 170 + l];
        out[(size_t)(r0 + row) * 4 + l] =
            s + b_logits[l] + (1.f - m) * -10000000000.0f;
    }
}

// ----------------------------------------------------------------------------
extern "C" void kernel_launch(void* const* d_in, const int* in_sizes, int n_in,
                              void* d_out, int out_size) {
    const float* inputs    = (const float*)d_in[0];
    const float* h_in      = (const float*)d_in[1];
    const float* c_in      = (const float*)d_in[2];
    const float* prof_emb  = (const float*)d_in[3];
    const float* skill_emb = (const float*)d_in[4];
    const float* eff_emb   = (const float*)d_in[5];
    const float* w0        = (const float*)d_in[6];
    const float* b0        = (const float*)d_in[7];
    const float* w1        = (const float*)d_in[8];
    const float* b1        = (const float*)d_in[9];
    const float* w_ih      = (const float*)d_in[10];
    const float* w_hh      = (const float*)d_in[11];
    const float* b_ih      = (const float*)d_in[12];
    const float* b_hh      = (const float*)d_in[13];
    const float* w_logits  = (const float*)d_in[14];
    const float* b_logits  = (const float*)d_in[15];
    float* out = (float*)d_out;

    int B = in_sizes[0] / 170;

    // sX + sH + sW + sWl + sIds + sIn
    const int smem_bytes =
        (2 * TM * AST + KT * 256 + 1024 + 256 + TM * 172 + 16) * 4; // ~198.7 KB
    cudaFuncSetAttribute(mlstm_fused_kernel,
                         cudaFuncAttributeMaxDynamicSharedMemorySize, smem_bytes);

    mlstm_prep_kernel<<<(512 * 1024) / 256, 256>>>(w_ih, w_hh);
    mlstm_fused_kernel<<<B / TM, NTHR, smem_bytes>>>(
        inputs, h_in, c_in, prof_emb, skill_emb, eff_emb,
        w0, b0, w1, b1, b_ih, b_hh, w_logits, b_logits, out, B);
}